// round 6
// baseline (speedup 1.0000x reference)
#include <cuda_runtime.h>
#include <cuda_fp16.h>
#include <math.h>
#include <stdint.h>

// ---------------- problem constants ----------------
#define THREADS   512
#define MROWS     128         // batch rows per CTA
#define D1        32
#define DFF       256
#define D2        32
#define NBINS     16
#define DOUT      1568        // 49*32
#define NCH       32          // one chunk per output j
#define HSTR      68          // h1T padded stride (floats)
#define PRMSTR    51          // prm stride (floats), odd -> conflict-free spline reads
#define TAILF     3.0f
#define MINVF     0.001f
#define EPSF      1e-6f

// ---------------- smem byte offsets ----------------
#define SM_A_HI   0                         // 128x256 f16, 512B/row, XOR16 swizzle (65536 B)
#define SM_A_LO   65536                     // 65536 B
#define SM_R      131072                    // scratch region
#define SM_X1     SM_R                      // 64x32 f32 = 8192 B    (phases 1-2)
#define SM_H1     (SM_R + 8192)             // 256x68 f32 = 69632 B  (phases 1-2; ends 208896)
#define SM_B      SM_R                      // B fragments 64 KB     (mma phase)
#define SM_PRM    (SM_R + 65536)            // 128x51 f32 = 26112 B
#define SM_B3     (SM_R + 65536 + 26112)    // 1568 f32 = 6272 B
#define SMEM_TOTAL (SM_B3 + 6272)           // 228992 B

typedef unsigned long long u64;

// prepped W3 fragments: [c][nt][kk][lane] -> uint4{hi_b0, hi_b1, lo_b0, lo_b1}
__device__ __align__(16) uint4 g_W3B[NCH * 8 * 16 * 32];   // 2 MB

// ---------------- helpers ----------------
__device__ __forceinline__ u64 pack2(float lo, float hi) {
    u64 r; asm("mov.b64 %0, {%1, %2};" : "=l"(r) : "f"(lo), "f"(hi)); return r;
}
__device__ __forceinline__ void unpack2(u64 v, float& lo, float& hi) {
    asm("mov.b64 {%0, %1}, %2;" : "=f"(lo), "=f"(hi) : "l"(v));
}
__device__ __forceinline__ void fma2(u64& d, u64 a, u64 b) {
    asm("fma.rn.f32x2 %0, %1, %2, %0;" : "+l"(d) : "l"(a), "l"(b));
}
__device__ __forceinline__ float softplusf(float x) {
    return fmaxf(x, 0.0f) + log1pf(__expf(-fabsf(x)));
}
__device__ __forceinline__ uint32_t smem_u32(const void* p) {
    uint32_t a;
    asm("{ .reg .u64 t; cvta.to.shared.u64 t, %1; cvt.u32.u64 %0, t; }" : "=r"(a) : "l"(p));
    return a;
}
#define NAMED_BAR(id, cnt) \
    asm volatile("bar.sync %0, %1;" :: "r"(id), "r"(cnt) : "memory")

// ---------------- tensor-core primitives (baseline ISA, sm_80+) ----------------
__device__ __forceinline__ void ldsm_x4(uint32_t addr, uint32_t r[4]) {
    asm volatile("ldmatrix.sync.aligned.m8n8.x4.shared.b16 {%0,%1,%2,%3}, [%4];"
                 : "=r"(r[0]), "=r"(r[1]), "=r"(r[2]), "=r"(r[3]) : "r"(addr));
}
__device__ __forceinline__ void mma16816(float d[4], const uint32_t a[4],
                                         uint32_t b0, uint32_t b1) {
    asm volatile("mma.sync.aligned.m16n8k16.row.col.f32.f16.f16.f32 "
                 "{%0,%1,%2,%3}, {%4,%5,%6,%7}, {%8,%9}, {%0,%1,%2,%3};"
                 : "+f"(d[0]), "+f"(d[1]), "+f"(d[2]), "+f"(d[3])
                 : "r"(a[0]), "r"(a[1]), "r"(a[2]), "r"(a[3]), "r"(b0), "r"(b1));
}
__device__ __forceinline__ uint32_t hpack(__half a, __half b) {
    uint32_t r;
    asm("mov.b32 %0, {%1, %2};" : "=r"(r) : "h"(__half_as_ushort(a)), "h"(__half_as_ushort(b)));
    return r;
}

// =====================================================================
// prep kernel: W3 [256 x 1568] -> per-lane hi/lo B fragments per chunk
// =====================================================================
__global__ void prep_w3_kernel(const float* __restrict__ W3) {
    int id = blockIdx.x * blockDim.x + threadIdx.x;
    if (id >= NCH * 8 * 16 * 32) return;
    const int lane = id & 31;
    const int kk   = (id >> 5) & 15;
    const int nt   = (id >> 9) & 7;
    const int c    = id >> 12;
    const int g = lane >> 2, tg = lane & 3;
    const int n = nt * 8 + g;
    float w00 = 0.f, w01 = 0.f, w10 = 0.f, w11 = 0.f;
    if (n < 49) {
        const size_t pi = (size_t)c * 49 + n;
        const int k0 = kk * 16 + 2 * tg;
        w00 = W3[(size_t)(k0    ) * DOUT + pi];
        w01 = W3[(size_t)(k0 + 1) * DOUT + pi];
        w10 = W3[(size_t)(k0 + 8) * DOUT + pi];
        w11 = W3[(size_t)(k0 + 9) * DOUT + pi];
    }
    const __half h00 = __float2half_rn(w00), h01 = __float2half_rn(w01);
    const __half h10 = __float2half_rn(w10), h11 = __float2half_rn(w11);
    const __half l00 = __float2half_rn(w00 - __half2float(h00));
    const __half l01 = __float2half_rn(w01 - __half2float(h01));
    const __half l10 = __float2half_rn(w10 - __half2float(h10));
    const __half l11 = __float2half_rn(w11 - __half2float(h11));
    uint4 v;
    v.x = hpack(h00, h01);
    v.y = hpack(h10, h11);
    v.z = hpack(l00, l01);
    v.w = hpack(l10, l11);
    g_W3B[id] = v;
}

// =====================================================================
// main fused kernel
// =====================================================================
__global__ __launch_bounds__(THREADS, 1)
void rq_fused_kernel(const float* __restrict__ x1,
                     const float* __restrict__ x2,
                     const float* __restrict__ W1,
                     const float* __restrict__ b1,
                     const float* __restrict__ W2,
                     const float* __restrict__ b2,
                     const float* __restrict__ b3,
                     float* __restrict__ zout,
                     float* __restrict__ ldout)
{
    extern __shared__ char smem[];
    const uint32_t sbase = smem_u32(smem);
    float* x1s = (float*)(smem + SM_X1);
    float* h1T = (float*)(smem + SM_H1);
    float* prm = (float*)(smem + SM_PRM);
    float* b3s = (float*)(smem + SM_B3);
    const uint4* Bsm = (const uint4*)(smem + SM_B);

    const int t    = threadIdx.x;
    const int wid  = t >> 5;
    const int lane = t & 31;
    const int col  = t & 255;     // owned MLP column in phases 1-2
    const int rh   = t >> 8;      // 0/1: 32-row half of the 64-row sub-block
    const int row0 = blockIdx.x * MROWS;

    // b3 -> smem (region disjoint from phase scratch)
    for (int i = t; i < DOUT; i += THREADS) b3s[i] = b3[i];

    // ---------------- phases 1+2 (SIMT fp32x2): 2 sub-blocks of 64 rows ----------------
    for (int sub = 0; sub < 2; sub++) {
        for (int i = t; i < 64 * D1; i += THREADS)
            x1s[i] = x1[(size_t)(row0 + sub * 64) * D1 + i];
        __syncthreads();

        // phase 1: h1 = relu(x1 @ W1 + b1)
        {
            float w1r[D1];
            #pragma unroll
            for (int k = 0; k < D1; k++) w1r[k] = W1[k * DFF + col];
            const float bb = b1[col];
            #pragma unroll
            for (int rr = 0; rr < 32; rr++) {
                const int r = rh * 32 + rr;
                float acc = bb;
                #pragma unroll
                for (int k = 0; k < D1; k++)
                    acc = fmaf(x1s[r * D1 + k], w1r[k], acc);
                h1T[col * HSTR + r] = fmaxf(acc, 0.0f);
            }
        }
        __syncthreads();

        // phase 2: h2 = relu(h1 @ W2 + b2) -> A_hi/A_lo f16 (XOR16-swizzled)
        {
            u64 acc2[16];
            const float bb = b2[col];
            #pragma unroll
            for (int q = 0; q < 16; q++) acc2[q] = pack2(bb, bb);
            #pragma unroll 4
            for (int k = 0; k < DFF; k++) {
                const float w = __ldg(W2 + k * DFF + col);
                const u64 w2 = pack2(w, w);
                const ulonglong2* h4 = reinterpret_cast<const ulonglong2*>(
                    h1T + k * HSTR + rh * 32);
                #pragma unroll
                for (int q = 0; q < 8; q++) {
                    ulonglong2 a = h4[q];
                    fma2(acc2[2*q + 0], a.x, w2);
                    fma2(acc2[2*q + 1], a.y, w2);
                }
            }
            #pragma unroll
            for (int q = 0; q < 16; q++) {
                float lo, hi;
                unpack2(acc2[q], lo, hi);
                #pragma unroll
                for (int e = 0; e < 2; e++) {
                    const float v = fmaxf(e ? hi : lo, 0.0f);
                    const int r = sub * 64 + rh * 32 + 2 * q + e;
                    const __half vh = __float2half_rn(v);
                    const __half vl = __float2half_rn(v - __half2float(vh));
                    const uint32_t ao = (uint32_t)(r * 512 + col * 2) ^ ((uint32_t)(r & 7) << 4);
                    *(__half*)(smem + SM_A_HI + ao) = vh;
                    *(__half*)(smem + SM_A_LO + ao) = vl;
                }
            }
        }
        __syncthreads();
    }

    // preload B chunk 0
    {
        const uint4* src = g_W3B;
        uint4* dst = (uint4*)(smem + SM_B);
        for (int i = t; i < 4096; i += THREADS) dst[i] = src[i];
    }
    __syncthreads();

    // =====================================================================
    // warp-specialized chunk pipeline:
    //   warps 0-7  : MMA (M=32 rows, N=32 cols each)
    //   warps 8-11 : spline for chunk c-1 (concurrent with MMA mainloop c)
    //   warps 12-15: B(c+1) prefetch (concurrent with MMA epilogue c)
    // bar 1 (384 thr: warps 0-11): prm free for epilogue
    // bar 2 (384 thr: warps 0-7,12-15): B reads done, copy may start
    // =====================================================================
    float ldsum = 0.0f;

    #pragma unroll 1
    for (int c = 0; c < NCH; c++) {
        if (wid < 8) {
            // ------------------ MMA warps ------------------
            const int mt = wid & 3;       // 32-row group
            const int nh = wid >> 2;      // 32-col group
            float d0[16], d1[16];
            #pragma unroll
            for (int i = 0; i < 16; i++) { d0[i] = 0.0f; d1[i] = 0.0f; }

            const uint32_t arow  = (uint32_t)(mt * 32 + (lane & 15));
            const uint32_t ab0   = arow * 512 + ((lane >> 4) << 4);
            const uint32_t ab1   = ab0 + 16 * 512;
            const uint32_t aswz  = (arow & 7) << 4;

            #pragma unroll 2
            for (int kk = 0; kk < 16; kk++) {
                const uint32_t o0 = (ab0 + kk * 32) ^ aswz;
                const uint32_t o1 = (ab1 + kk * 32) ^ aswz;
                uint32_t a0h[4], a0l[4], a1h[4], a1l[4];
                ldsm_x4(sbase + SM_A_HI + o0, a0h);
                ldsm_x4(sbase + SM_A_HI + o1, a1h);
                ldsm_x4(sbase + SM_A_LO + o0, a0l);
                ldsm_x4(sbase + SM_A_LO + o1, a1l);
                uint4 bb[4];
                #pragma unroll
                for (int nt4 = 0; nt4 < 4; nt4++)
                    bb[nt4] = Bsm[((nh * 4 + nt4) * 16 + kk) * 32 + lane];
                // product-major ordering: same-accumulator reuse distance = 8 MMAs
                #pragma unroll
                for (int nt4 = 0; nt4 < 4; nt4++)
                    mma16816(d0 + nt4 * 4, a0h, bb[nt4].x, bb[nt4].y);   // hi*hi, rows 0-15
                #pragma unroll
                for (int nt4 = 0; nt4 < 4; nt4++)
                    mma16816(d1 + nt4 * 4, a1h, bb[nt4].x, bb[nt4].y);   // hi*hi, rows 16-31
                #pragma unroll
                for (int nt4 = 0; nt4 < 4; nt4++)
                    mma16816(d0 + nt4 * 4, a0h, bb[nt4].z, bb[nt4].w);   // hi*lo
                #pragma unroll
                for (int nt4 = 0; nt4 < 4; nt4++)
                    mma16816(d1 + nt4 * 4, a1h, bb[nt4].z, bb[nt4].w);
                #pragma unroll
                for (int nt4 = 0; nt4 < 4; nt4++)
                    mma16816(d0 + nt4 * 4, a0l, bb[nt4].x, bb[nt4].y);   // lo*hi
                #pragma unroll
                for (int nt4 = 0; nt4 < 4; nt4++)
                    mma16816(d1 + nt4 * 4, a1l, bb[nt4].x, bb[nt4].y);
            }

            NAMED_BAR(2, 384);   // B(c) reads done -> copy warps go
            NAMED_BAR(1, 384);   // spline(c-1) done -> prm free

            // epilogue: D + b3 -> prm
            {
                const int g = lane >> 2, tg = lane & 3;
                const float* b3c = b3s + c * 49;
                #pragma unroll
                for (int mtile = 0; mtile < 2; mtile++) {
                    const float* dd = mtile ? d1 : d0;
                    const int r0 = mt * 32 + mtile * 16 + g;
                    const int r1 = r0 + 8;
                    #pragma unroll
                    for (int nt4 = 0; nt4 < 4; nt4++) {
                        const int n0 = nh * 32 + nt4 * 8 + 2 * tg;
                        if (n0 < 49) {
                            const float bv = b3c[n0];
                            prm[r0 * PRMSTR + n0] = dd[nt4*4 + 0] + bv;
                            prm[r1 * PRMSTR + n0] = dd[nt4*4 + 2] + bv;
                        }
                        if (n0 + 1 < 49) {
                            const float bv = b3c[n0 + 1];
                            prm[r0 * PRMSTR + n0 + 1] = dd[nt4*4 + 1] + bv;
                            prm[r1 * PRMSTR + n0 + 1] = dd[nt4*4 + 3] + bv;
                        }
                    }
                }
            }
        } else if (wid < 12) {
            // ------------------ spline warps: chunk c-1 ------------------
            if (c > 0) {
                const int rr   = t - 256;          // 0..127
                const int grow = row0 + rr;
                const int j    = c - 1;
                const float* pp = prm + rr * PRMSTR;

                const float x = __ldg(x2 + (size_t)grow * D2 + j);
                const bool inside = (x >= -TAILF) && (x <= TAILF);
                const float xc = fminf(fmaxf(x, -TAILF), TAILF);

                float mw = -1e30f, mh = -1e30f;
                #pragma unroll
                for (int i = 0; i < NBINS; i++) {
                    mw = fmaxf(mw, pp[i]);
                    mh = fmaxf(mh, pp[NBINS + i]);
                }
                float ew[NBINS], eh[NBINS];
                float sw = 0.0f, sh = 0.0f;
                #pragma unroll
                for (int i = 0; i < NBINS; i++) {
                    ew[i] = __expf(pp[i] - mw);          sw += ew[i];
                    eh[i] = __expf(pp[NBINS + i] - mh);  sh += eh[i];
                }
                const float cscale = 1.0f - NBINS * MINVF;
                const float rw = cscale / sw;
                const float rhh = cscale / sh;

                float S = 0.0f;
                float cw_lo = -TAILF, cw_lo_prev = -TAILF, cw_hi = TAILF;
                int idx = 0;
                bool failed = false;
                #pragma unroll
                for (int m = 1; m <= NBINS; m++) {
                    S += MINVF + rw * ew[m - 1];
                    const float cwm = fmaf(2.0f * TAILF, S, -TAILF);
                    const float ref = (m == NBINS) ? (cwm + EPSF) : cwm;
                    if (ref <= xc) { idx = m; cw_lo_prev = cw_lo; cw_lo = cwm; }
                    else if (!failed) { failed = true; cw_hi = cwm; }
                }
                if (!failed) { idx = NBINS - 1; cw_hi = cw_lo; cw_lo = cw_lo_prev; }

                float Sh = 0.0f;
                float ch_lo = -TAILF, ch_hi = TAILF;
                #pragma unroll
                for (int m = 1; m <= NBINS; m++) {
                    Sh += MINVF + rhh * eh[m - 1];
                    const float chm = fmaf(2.0f * TAILF, Sh, -TAILF);
                    if (m == idx)     ch_lo = chm;
                    if (m == idx + 1) ch_hi = chm;
                }

                const float dd0 = MINVF + softplusf(pp[2 * NBINS + idx]);
                const float dd1 = MINVF + softplusf(pp[2 * NBINS + idx + 1]);

                const float xkd = cw_hi - cw_lo;
                const float ykd = ch_hi - ch_lo;
                const float sk  = ykd / xkd;
                const float xi  = (xc - cw_lo) / xkd;
                const float xi1m = xi * (1.0f - xi);
                const float alpha = ykd * (sk * xi * xi + dd0 * xi1m);
                const float beta  = sk + (dd1 + dd0 - 2.0f * sk) * xi1m;
                const float z     = ch_lo + alpha / beta;
                const float omxi  = 1.0f - xi;
                const float dnum  = sk * sk * (dd1 * xi * xi + 2.0f * sk * xi1m + dd0 * omxi * omxi);
                const float ld = __logf(dnum) - 2.0f * __logf(beta);

                zout[(size_t)grow * D2 + j] = inside ? z : x;
                ldsum += inside ? ld : 0.0f;
            }
            NAMED_BAR(1, 384);   // prm free
        } else {
            // ------------------ copy warps: B(c+1) ------------------
            NAMED_BAR(2, 384);   // wait MMA done reading B(c)
            if (c + 1 < NCH) {
                const uint4* src = g_W3B + (size_t)(c + 1) * 4096;
                uint4* dst = (uint4*)(smem + SM_B);
                const int i0 = t - 384;
                #pragma unroll
                for (int q = 0; q < 32; q++)
                    dst[i0 + q * 128] = src[i0 + q * 128];
            }
        }
        __syncthreads();   // prm(c) visible, B(c+1) ready, spline aligned
    }

    // final spline: chunk NCH-1 (prm still holds it)
    if (wid >= 8 && wid < 12) {
        const int rr   = t - 256;
        const int grow = row0 + rr;
        const int j    = NCH - 1;
        const float* pp = prm + rr * PRMSTR;

        const float x = __ldg(x2 + (size_t)grow * D2 + j);
        const bool inside = (x >= -TAILF) && (x <= TAILF);
        const float xc = fminf(fmaxf(x, -TAILF), TAILF);

        float mw = -1e30f, mh = -1e30f;
        #pragma unroll
        for (int i = 0; i < NBINS; i++) {
            mw = fmaxf(mw, pp[i]);
            mh = fmaxf(mh, pp[NBINS + i]);
        }
        float ew[NBINS], eh[NBINS];
        float sw = 0.0f, sh = 0.0f;
        #pragma unroll
        for (int i = 0; i < NBINS; i++) {
            ew[i] = __expf(pp[i] - mw);          sw += ew[i];
            eh[i] = __expf(pp[NBINS + i] - mh);  sh += eh[i];
        }
        const float cscale = 1.0f - NBINS * MINVF;
        const float rw = cscale / sw;
        const float rhh = cscale / sh;

        float S = 0.0f;
        float cw_lo = -TAILF, cw_lo_prev = -TAILF, cw_hi = TAILF;
        int idx = 0;
        bool failed = false;
        #pragma unroll
        for (int m = 1; m <= NBINS; m++) {
            S += MINVF + rw * ew[m - 1];
            const float cwm = fmaf(2.0f * TAILF, S, -TAILF);
            const float ref = (m == NBINS) ? (cwm + EPSF) : cwm;
            if (ref <= xc) { idx = m; cw_lo_prev = cw_lo; cw_lo = cwm; }
            else if (!failed) { failed = true; cw_hi = cwm; }
        }
        if (!failed) { idx = NBINS - 1; cw_hi = cw_lo; cw_lo = cw_lo_prev; }

        float Sh = 0.0f;
        float ch_lo = -TAILF, ch_hi = TAILF;
        #pragma unroll
        for (int m = 1; m <= NBINS; m++) {
            Sh += MINVF + rhh * eh[m - 1];
            const float chm = fmaf(2.0f * TAILF, Sh, -TAILF);
            if (m == idx)     ch_lo = chm;
            if (m == idx + 1) ch_hi = chm;
        }

        const float dd0 = MINVF + softplusf(pp[2 * NBINS + idx]);
        const float dd1 = MINVF + softplusf(pp[2 * NBINS + idx + 1]);

        const float xkd = cw_hi - cw_lo;
        const float ykd = ch_hi - ch_lo;
        const float sk  = ykd / xkd;
        const float xi  = (xc - cw_lo) / xkd;
        const float xi1m = xi * (1.0f - xi);
        const float alpha = ykd * (sk * xi * xi + dd0 * xi1m);
        const float beta  = sk + (dd1 + dd0 - 2.0f * sk) * xi1m;
        const float z     = ch_lo + alpha / beta;
        const float omxi  = 1.0f - xi;
        const float dnum  = sk * sk * (dd1 * xi * xi + 2.0f * sk * xi1m + dd0 * omxi * omxi);
        const float ld = __logf(dnum) - 2.0f * __logf(beta);

        zout[(size_t)grow * D2 + j] = inside ? z : x;
        ldsum += inside ? ld : 0.0f;

        ldout[grow] = ldsum;
    }
}

extern "C" void kernel_launch(void* const* d_in, const int* in_sizes, int n_in,
                              void* d_out, int out_size)
{
    const float* x1 = (const float*)d_in[0];
    const float* x2 = (const float*)d_in[1];
    const float* W1 = (const float*)d_in[2];
    const float* b1 = (const float*)d_in[3];
    const float* W2 = (const float*)d_in[4];
    const float* b2 = (const float*)d_in[5];
    const float* W3 = (const float*)d_in[6];
    const float* b3 = (const float*)d_in[7];

    float* out = (float*)d_out;
    const int B = in_sizes[0] / D1;         // 65536
    float* zout  = out;
    float* ldout = out + (size_t)B * D2;

    prep_w3_kernel<<<(NCH * 8 * 16 * 32 + 255) / 256, 256>>>(W3);

    cudaFuncSetAttribute(rq_fused_kernel,
                         cudaFuncAttributeMaxDynamicSharedMemorySize, SMEM_TOTAL);
    rq_fused_kernel<<<B / MROWS, THREADS, SMEM_TOTAL>>>(
        x1, x2, W1, b1, W2, b2, b3, zout, ldout);
}

// round 7
// speedup vs baseline: 1.0439x; 1.0439x over previous
#include <cuda_runtime.h>
#include <cuda_fp16.h>
#include <math.h>
#include <stdint.h>

// ---------------- problem constants ----------------
#define THREADS   640
#define MROWS     128         // batch rows per CTA
#define D1        32
#define DFF       256
#define D2        32
#define NBINS     16
#define DOUT      1568        // 49*32
#define NCH       32          // one chunk per output j
#define HSTR      68          // h1T padded stride (floats)
#define PRMSTR    51          // prm stride (floats), odd -> conflict-free spline reads
#define TAILF     3.0f
#define MINVF     0.001f
#define EPSF      1e-6f

// ---------------- smem byte offsets ----------------
#define SM_A_HI   0                         // 128x256 f16, 512B/row, XOR16 swizzle (65536 B)
#define SM_A_LO   65536                     // 65536 B
#define SM_R      131072                    // scratch region
#define SM_X1     SM_R                      // 64x32 f32 = 8192 B    (phases 1-2)
#define SM_H1     (SM_R + 8192)             // 256x68 f32 = 69632 B  (phases 1-2)
#define SM_B      SM_R                      // B fragments 64 KB     (mma phase)
#define SM_PRM    (SM_R + 65536)            // 128x51 f32 = 26112 B
#define SM_B3     (SM_R + 65536 + 26112)    // 1568 f32 = 6272 B
#define SMEM_TOTAL (SM_B3 + 6272)           // 228992 B

typedef unsigned long long u64;

// prepped W3 fragments: [c][nt][kk][lane] -> uint4{hi_b0, hi_b1, lo_b0, lo_b1}
__device__ __align__(16) uint4 g_W3B[NCH * 8 * 16 * 32];   // 2 MB

// ---------------- helpers ----------------
__device__ __forceinline__ u64 pack2(float lo, float hi) {
    u64 r; asm("mov.b64 %0, {%1, %2};" : "=l"(r) : "f"(lo), "f"(hi)); return r;
}
__device__ __forceinline__ void unpack2(u64 v, float& lo, float& hi) {
    asm("mov.b64 {%0, %1}, %2;" : "=f"(lo), "=f"(hi) : "l"(v));
}
__device__ __forceinline__ void fma2(u64& d, u64 a, u64 b) {
    asm("fma.rn.f32x2 %0, %1, %2, %0;" : "+l"(d) : "l"(a), "l"(b));
}
__device__ __forceinline__ float softplusf(float x) {
    return fmaxf(x, 0.0f) + log1pf(__expf(-fabsf(x)));
}
__device__ __forceinline__ uint32_t smem_u32(const void* p) {
    uint32_t a;
    asm("{ .reg .u64 t; cvta.to.shared.u64 t, %1; cvt.u32.u64 %0, t; }" : "=r"(a) : "l"(p));
    return a;
}
#define CP_ASYNC16(dst, src) \
    asm volatile("cp.async.cg.shared.global [%0], [%1], 16;" :: "r"(dst), "l"(src))
#define CP_COMMIT() asm volatile("cp.async.commit_group;" ::: "memory")
#define CP_WAIT0()  asm volatile("cp.async.wait_group 0;" ::: "memory")

// ---------------- tensor-core primitives (baseline ISA, sm_80+) ----------------
__device__ __forceinline__ void ldsm_x4(uint32_t addr, uint32_t r[4]) {
    asm volatile("ldmatrix.sync.aligned.m8n8.x4.shared.b16 {%0,%1,%2,%3}, [%4];"
                 : "=r"(r[0]), "=r"(r[1]), "=r"(r[2]), "=r"(r[3]) : "r"(addr));
}
__device__ __forceinline__ void mma16816(float d[4], const uint32_t a[4],
                                         uint32_t b0, uint32_t b1) {
    asm volatile("mma.sync.aligned.m16n8k16.row.col.f32.f16.f16.f32 "
                 "{%0,%1,%2,%3}, {%4,%5,%6,%7}, {%8,%9}, {%0,%1,%2,%3};"
                 : "+f"(d[0]), "+f"(d[1]), "+f"(d[2]), "+f"(d[3])
                 : "r"(a[0]), "r"(a[1]), "r"(a[2]), "r"(a[3]), "r"(b0), "r"(b1));
}
__device__ __forceinline__ uint32_t hpack(__half a, __half b) {
    uint32_t r;
    asm("mov.b32 %0, {%1, %2};" : "=r"(r) : "h"(__half_as_ushort(a)), "h"(__half_as_ushort(b)));
    return r;
}

// =====================================================================
// prep kernel: W3 [256 x 1568] -> per-lane hi/lo B fragments per chunk
// =====================================================================
__global__ void prep_w3_kernel(const float* __restrict__ W3) {
    int id = blockIdx.x * blockDim.x + threadIdx.x;
    if (id >= NCH * 8 * 16 * 32) return;
    const int lane = id & 31;
    const int kk   = (id >> 5) & 15;
    const int nt   = (id >> 9) & 7;
    const int c    = id >> 12;
    const int g = lane >> 2, tg = lane & 3;
    const int n = nt * 8 + g;
    float w00 = 0.f, w01 = 0.f, w10 = 0.f, w11 = 0.f;
    if (n < 49) {
        const size_t pi = (size_t)c * 49 + n;
        const int k0 = kk * 16 + 2 * tg;
        w00 = W3[(size_t)(k0    ) * DOUT + pi];
        w01 = W3[(size_t)(k0 + 1) * DOUT + pi];
        w10 = W3[(size_t)(k0 + 8) * DOUT + pi];
        w11 = W3[(size_t)(k0 + 9) * DOUT + pi];
    }
    const __half h00 = __float2half_rn(w00), h01 = __float2half_rn(w01);
    const __half h10 = __float2half_rn(w10), h11 = __float2half_rn(w11);
    const __half l00 = __float2half_rn(w00 - __half2float(h00));
    const __half l01 = __float2half_rn(w01 - __half2float(h01));
    const __half l10 = __float2half_rn(w10 - __half2float(h10));
    const __half l11 = __float2half_rn(w11 - __half2float(h11));
    uint4 v;
    v.x = hpack(h00, h01);
    v.y = hpack(h10, h11);
    v.z = hpack(l00, l01);
    v.w = hpack(l10, l11);
    g_W3B[id] = v;
}

// =====================================================================
// main fused kernel
// =====================================================================
__global__ __launch_bounds__(THREADS, 1)
void rq_fused_kernel(const float* __restrict__ x1,
                     const float* __restrict__ x2,
                     const float* __restrict__ W1,
                     const float* __restrict__ b1,
                     const float* __restrict__ W2,
                     const float* __restrict__ b2,
                     const float* __restrict__ b3,
                     float* __restrict__ zout,
                     float* __restrict__ ldout)
{
    extern __shared__ char smem[];
    const uint32_t sbase = smem_u32(smem);
    float* x1s = (float*)(smem + SM_X1);
    float* h1T = (float*)(smem + SM_H1);
    float* prm = (float*)(smem + SM_PRM);
    float* b3s = (float*)(smem + SM_B3);
    const uint4* Bsm = (const uint4*)(smem + SM_B);

    const int t    = threadIdx.x;
    const int wid  = t >> 5;
    const int lane = t & 31;
    const int col  = t & 255;     // owned MLP column in phases 1-2 (warps 0-15)
    const int rh   = (t >> 8) & 1;
    const int row0 = blockIdx.x * MROWS;

    // b3 -> smem (region disjoint from phase scratch)
    for (int i = t; i < DOUT; i += THREADS) b3s[i] = b3[i];

    // ---------------- phases 1+2 (SIMT fp32x2, warps 0-15): 2 sub-blocks of 64 rows ----
    for (int sub = 0; sub < 2; sub++) {
        if (t < 512)
            for (int i = t; i < 64 * D1; i += 512)
                x1s[i] = x1[(size_t)(row0 + sub * 64) * D1 + i];
        __syncthreads();

        if (t < 512) {
            // phase 1: h1 = relu(x1 @ W1 + b1)
            float w1r[D1];
            #pragma unroll
            for (int k = 0; k < D1; k++) w1r[k] = W1[k * DFF + col];
            const float bb = b1[col];
            #pragma unroll
            for (int rr = 0; rr < 32; rr++) {
                const int r = rh * 32 + rr;
                float acc = bb;
                #pragma unroll
                for (int k = 0; k < D1; k++)
                    acc = fmaf(x1s[r * D1 + k], w1r[k], acc);
                h1T[col * HSTR + r] = fmaxf(acc, 0.0f);
            }
        }
        __syncthreads();

        if (t < 512) {
            // phase 2: h2 = relu(h1 @ W2 + b2) -> A_hi/A_lo f16 (XOR16-swizzled)
            u64 acc2[16];
            const float bb = b2[col];
            #pragma unroll
            for (int q = 0; q < 16; q++) acc2[q] = pack2(bb, bb);
            #pragma unroll 4
            for (int k = 0; k < DFF; k++) {
                const float w = __ldg(W2 + k * DFF + col);
                const u64 w2 = pack2(w, w);
                const ulonglong2* h4 = reinterpret_cast<const ulonglong2*>(
                    h1T + k * HSTR + rh * 32);
                #pragma unroll
                for (int q = 0; q < 8; q++) {
                    ulonglong2 a = h4[q];
                    fma2(acc2[2*q + 0], a.x, w2);
                    fma2(acc2[2*q + 1], a.y, w2);
                }
            }
            #pragma unroll
            for (int q = 0; q < 16; q++) {
                float lo, hi;
                unpack2(acc2[q], lo, hi);
                #pragma unroll
                for (int e = 0; e < 2; e++) {
                    const float v = fmaxf(e ? hi : lo, 0.0f);
                    const int r = sub * 64 + rh * 32 + 2 * q + e;
                    const __half vh = __float2half_rn(v);
                    const __half vl = __float2half_rn(v - __half2float(vh));
                    const uint32_t ao = (uint32_t)(r * 512 + col * 2) ^ ((uint32_t)(r & 7) << 4);
                    *(__half*)(smem + SM_A_HI + ao) = vh;
                    *(__half*)(smem + SM_A_LO + ao) = vl;
                }
            }
        }
        __syncthreads();
    }

    // preload B chunk 0 via cp.async
    {
        const uint4* src = g_W3B;
        for (int i = t; i < 4096; i += THREADS)
            CP_ASYNC16(sbase + SM_B + i * 16, (const void*)(src + i));
        CP_COMMIT(); CP_WAIT0();
    }
    __syncthreads();

    // =====================================================================
    // chunk pipeline:
    //   warps 0-15 : MMA (M=16 rows, N=32 cols each), software-pipelined frags
    //   warps 16-19: spline for chunk c-1 (concurrent with MMA mainloop c)
    //   all        : cp.async B(c+1) after mid-sync (overlaps epilogue)
    // =====================================================================
    float ldsum = 0.0f;

    // fixed per-thread MMA addressing
    const int mt = wid & 7;       // 16-row M-tile
    const int nh = wid >> 3;      // 32-col N-half
    const uint32_t arow  = (uint32_t)(mt * 16 + (lane & 15));
    const uint32_t abase = arow * 512 + ((lane >> 4) << 4);
    const uint32_t aswz  = (arow & 7) << 4;

    #pragma unroll 1
    for (int c = 0; c < NCH; c++) {
        float d[16];
        if (wid < 16) {
            // ------------------ MMA mainloop, double-buffered fragments --------------
            #pragma unroll
            for (int i = 0; i < 16; i++) d[i] = 0.0f;

            uint32_t ah[2][4], al[2][4];
            uint4 bb[2][4];
            {   // preload kk = 0
                const uint32_t o = abase ^ aswz;
                ldsm_x4(sbase + SM_A_HI + o, ah[0]);
                ldsm_x4(sbase + SM_A_LO + o, al[0]);
                #pragma unroll
                for (int nt4 = 0; nt4 < 4; nt4++)
                    bb[0][nt4] = Bsm[((nh * 4 + nt4) * 16 + 0) * 32 + lane];
            }
            #pragma unroll
            for (int kk = 0; kk < 16; kk++) {
                const int cur = kk & 1, nxt = cur ^ 1;
                if (kk < 15) {
                    const uint32_t o = (abase + (kk + 1) * 32) ^ aswz;
                    ldsm_x4(sbase + SM_A_HI + o, ah[nxt]);
                    ldsm_x4(sbase + SM_A_LO + o, al[nxt]);
                    #pragma unroll
                    for (int nt4 = 0; nt4 < 4; nt4++)
                        bb[nxt][nt4] = Bsm[((nh * 4 + nt4) * 16 + (kk + 1)) * 32 + lane];
                }
                #pragma unroll
                for (int nt4 = 0; nt4 < 4; nt4++) {
                    mma16816(d + nt4 * 4, ah[cur], bb[cur][nt4].x, bb[cur][nt4].y); // hi*hi
                    mma16816(d + nt4 * 4, ah[cur], bb[cur][nt4].z, bb[cur][nt4].w); // hi*lo
                    mma16816(d + nt4 * 4, al[cur], bb[cur][nt4].x, bb[cur][nt4].y); // lo*hi
                }
            }
        } else if (c > 0) {
            // ------------------ spline warps: chunk c-1 ------------------
            const int rr   = t - 512;          // 0..127
            const int grow = row0 + rr;
            const int j    = c - 1;
            const float* pp = prm + rr * PRMSTR;

            const float x = __ldg(x2 + (size_t)grow * D2 + j);
            const bool inside = (x >= -TAILF) && (x <= TAILF);
            const float xc = fminf(fmaxf(x, -TAILF), TAILF);

            float mw = -1e30f, mh = -1e30f;
            #pragma unroll
            for (int i = 0; i < NBINS; i++) {
                mw = fmaxf(mw, pp[i]);
                mh = fmaxf(mh, pp[NBINS + i]);
            }
            float ew[NBINS], eh[NBINS];
            float sw = 0.0f, sh = 0.0f;
            #pragma unroll
            for (int i = 0; i < NBINS; i++) {
                ew[i] = __expf(pp[i] - mw);          sw += ew[i];
                eh[i] = __expf(pp[NBINS + i] - mh);  sh += eh[i];
            }
            const float cscale = 1.0f - NBINS * MINVF;
            const float rw = cscale / sw;
            const float rhh = cscale / sh;

            float S = 0.0f;
            float cw_lo = -TAILF, cw_lo_prev = -TAILF, cw_hi = TAILF;
            int idx = 0;
            bool failed = false;
            #pragma unroll
            for (int m = 1; m <= NBINS; m++) {
                S += MINVF + rw * ew[m - 1];
                const float cwm = fmaf(2.0f * TAILF, S, -TAILF);
                const float ref = (m == NBINS) ? (cwm + EPSF) : cwm;
                if (ref <= xc) { idx = m; cw_lo_prev = cw_lo; cw_lo = cwm; }
                else if (!failed) { failed = true; cw_hi = cwm; }
            }
            if (!failed) { idx = NBINS - 1; cw_hi = cw_lo; cw_lo = cw_lo_prev; }

            float Sh = 0.0f;
            float ch_lo = -TAILF, ch_hi = TAILF;
            #pragma unroll
            for (int m = 1; m <= NBINS; m++) {
                Sh += MINVF + rhh * eh[m - 1];
                const float chm = fmaf(2.0f * TAILF, Sh, -TAILF);
                if (m == idx)     ch_lo = chm;
                if (m == idx + 1) ch_hi = chm;
            }

            const float dd0 = MINVF + softplusf(pp[2 * NBINS + idx]);
            const float dd1 = MINVF + softplusf(pp[2 * NBINS + idx + 1]);

            const float xkd = cw_hi - cw_lo;
            const float ykd = ch_hi - ch_lo;
            const float sk  = ykd / xkd;
            const float xi  = (xc - cw_lo) / xkd;
            const float xi1m = xi * (1.0f - xi);
            const float alpha = ykd * (sk * xi * xi + dd0 * xi1m);
            const float beta  = sk + (dd1 + dd0 - 2.0f * sk) * xi1m;
            const float z     = ch_lo + alpha / beta;
            const float omxi  = 1.0f - xi;
            const float dnum  = sk * sk * (dd1 * xi * xi + 2.0f * sk * xi1m + dd0 * omxi * omxi);
            const float ld = __logf(dnum) - 2.0f * __logf(beta);

            zout[(size_t)grow * D2 + j] = inside ? z : x;
            ldsum += inside ? ld : 0.0f;
        }
        __syncthreads();   // mid-sync: B(c) reads done, spline(c-1) done (prm free)

        // all threads: kick off B(c+1) prefetch (completes before end-sync)
        if (c + 1 < NCH) {
            const uint4* src = g_W3B + (size_t)(c + 1) * 4096;
            for (int i = t; i < 4096; i += THREADS)
                CP_ASYNC16(sbase + SM_B + i * 16, (const void*)(src + i));
        }
        CP_COMMIT();

        if (wid < 16) {
            // ------------------ epilogue: D + b3 -> prm ------------------
            const int g = lane >> 2, tg = lane & 3;
            const int r0 = mt * 16 + g, r1 = r0 + 8;
            const float* b3c = b3s + c * 49;
            #pragma unroll
            for (int nt4 = 0; nt4 < 4; nt4++) {
                const int n0 = nh * 32 + nt4 * 8 + 2 * tg;
                if (n0 < 49) {
                    const float bv = b3c[n0];
                    prm[r0 * PRMSTR + n0] = d[nt4*4 + 0] + bv;
                    prm[r1 * PRMSTR + n0] = d[nt4*4 + 2] + bv;
                }
                if (n0 + 1 < 49) {
                    const float bv = b3c[n0 + 1];
                    prm[r0 * PRMSTR + n0 + 1] = d[nt4*4 + 1] + bv;
                    prm[r1 * PRMSTR + n0 + 1] = d[nt4*4 + 3] + bv;
                }
            }
        }

        CP_WAIT0();
        __syncthreads();   // end-sync: prm(c) visible, B(c+1) ready
    }

    // final spline: chunk NCH-1
    if (wid >= 16) {
        const int rr   = t - 512;
        const int grow = row0 + rr;
        const int j    = NCH - 1;
        const float* pp = prm + rr * PRMSTR;

        const float x = __ldg(x2 + (size_t)grow * D2 + j);
        const bool inside = (x >= -TAILF) && (x <= TAILF);
        const float xc = fminf(fmaxf(x, -TAILF), TAILF);

        float mw = -1e30f, mh = -1e30f;
        #pragma unroll
        for (int i = 0; i < NBINS; i++) {
            mw = fmaxf(mw, pp[i]);
            mh = fmaxf(mh, pp[NBINS + i]);
        }
        float ew[NBINS], eh[NBINS];
        float sw = 0.0f, sh = 0.0f;
        #pragma unroll
        for (int i = 0; i < NBINS; i++) {
            ew[i] = __expf(pp[i] - mw);          sw += ew[i];
            eh[i] = __expf(pp[NBINS + i] - mh);  sh += eh[i];
        }
        const float cscale = 1.0f - NBINS * MINVF;
        const float rw = cscale / sw;
        const float rhh = cscale / sh;

        float S = 0.0f;
        float cw_lo = -TAILF, cw_lo_prev = -TAILF, cw_hi = TAILF;
        int idx = 0;
        bool failed = false;
        #pragma unroll
        for (int m = 1; m <= NBINS; m++) {
            S += MINVF + rw * ew[m - 1];
            const float cwm = fmaf(2.0f * TAILF, S, -TAILF);
            const float ref = (m == NBINS) ? (cwm + EPSF) : cwm;
            if (ref <= xc) { idx = m; cw_lo_prev = cw_lo; cw_lo = cwm; }
            else if (!failed) { failed = true; cw_hi = cwm; }
        }
        if (!failed) { idx = NBINS - 1; cw_hi = cw_lo; cw_lo = cw_lo_prev; }

        float Sh = 0.0f;
        float ch_lo = -TAILF, ch_hi = TAILF;
        #pragma unroll
        for (int m = 1; m <= NBINS; m++) {
            Sh += MINVF + rhh * eh[m - 1];
            const float chm = fmaf(2.0f * TAILF, Sh, -TAILF);
            if (m == idx)     ch_lo = chm;
            if (m == idx + 1) ch_hi = chm;
        }

        const float dd0 = MINVF + softplusf(pp[2 * NBINS + idx]);
        const float dd1 = MINVF + softplusf(pp[2 * NBINS + idx + 1]);

        const float xkd = cw_hi - cw_lo;
        const float ykd = ch_hi - ch_lo;
        const float sk  = ykd / xkd;
        const float xi  = (xc - cw_lo) / xkd;
        const float xi1m = xi * (1.0f - xi);
        const float alpha = ykd * (sk * xi * xi + dd0 * xi1m);
        const float beta  = sk + (dd1 + dd0 - 2.0f * sk) * xi1m;
        const float z     = ch_lo + alpha / beta;
        const float omxi  = 1.0f - xi;
        const float dnum  = sk * sk * (dd1 * xi * xi + 2.0f * sk * xi1m + dd0 * omxi * omxi);
        const float ld = __logf(dnum) - 2.0f * __logf(beta);

        zout[(size_t)grow * D2 + j] = inside ? z : x;
        ldsum += inside ? ld : 0.0f;

        ldout[grow] = ldsum;
    }
}

extern "C" void kernel_launch(void* const* d_in, const int* in_sizes, int n_in,
                              void* d_out, int out_size)
{
    const float* x1 = (const float*)d_in[0];
    const float* x2 = (const float*)d_in[1];
    const float* W1 = (const float*)d_in[2];
    const float* b1 = (const float*)d_in[3];
    const float* W2 = (const float*)d_in[4];
    const float* b2 = (const float*)d_in[5];
    const float* W3 = (const float*)d_in[6];
    const float* b3 = (const float*)d_in[7];

    float* out = (float*)d_out;
    const int B = in_sizes[0] / D1;         // 65536
    float* zout  = out;
    float* ldout = out + (size_t)B * D2;

    prep_w3_kernel<<<(NCH * 8 * 16 * 32 + 255) / 256, 256>>>(W3);

    cudaFuncSetAttribute(rq_fused_kernel,
                         cudaFuncAttributeMaxDynamicSharedMemorySize, SMEM_TOTAL);
    rq_fused_kernel<<<B / MROWS, THREADS, SMEM_TOTAL>>>(
        x1, x2, W1, b1, W2, b2, b3, zout, ldout);
}

// round 9
// speedup vs baseline: 1.3001x; 1.2454x over previous
#include <cuda_runtime.h>
#include <cuda_fp16.h>
#include <math.h>
#include <stdint.h>

// ---------------- problem constants ----------------
#define THREADS   640
#define MROWS     128         // batch rows per CTA
#define D1        32
#define DFF       256
#define D2        32
#define NBINS     16
#define DOUT      1568        // 49*32
#define NCH       32          // one chunk per output j
#define HSTR      68          // h1T padded stride (floats)
#define PRMSTR    51          // prm stride (floats), odd -> conflict-free spline reads
#define TAILF     3.0f
#define MINVF     0.001f
#define EPSF      1e-6f

// ---------------- smem byte offsets ----------------
#define SM_A_HI   0                         // 128x256 f16, 512B/row, XOR16 swizzle (65536 B)
#define SM_A_LO   65536                     // 65536 B
#define SM_R      131072                    // scratch region
#define SM_X1     SM_R                      // 64x32 f32 = 8192 B    (phases 1-2)
#define SM_H1     (SM_R + 8192)             // 256x68 f32 = 69632 B  (phases 1-2)
#define SM_B0     SM_R                      // B buf 0: 32768 B      (mma phase)
#define SM_B1     (SM_R + 32768)            // B buf 1: 32768 B
#define SM_PRM    (SM_R + 65536)            // 128x51 f32 = 26112 B
#define SM_B3     (SM_R + 65536 + 26112)    // 1568 f32 = 6272 B
#define SMEM_TOTAL (SM_B3 + 6272)           // 228992 B

// B tile size: 8*16*32 uint2 = 4096 uint2 = 2048 uint4 = 32768 B
#define B_TILE_U4 2048

typedef unsigned long long u64;

// prepped W3 hi-fragments: [c][nt][kk][lane] -> uint2{hi_b0, hi_b1}  (B-lo dropped)
__device__ __align__(16) uint2 g_W3B[NCH * 8 * 16 * 32];   // 1 MB

// ---------------- helpers ----------------
__device__ __forceinline__ u64 pack2(float lo, float hi) {
    u64 r; asm("mov.b64 %0, {%1, %2};" : "=l"(r) : "f"(lo), "f"(hi)); return r;
}
__device__ __forceinline__ void unpack2(u64 v, float& lo, float& hi) {
    asm("mov.b64 {%0, %1}, %2;" : "=f"(lo), "=f"(hi) : "l"(v));
}
__device__ __forceinline__ void fma2(u64& d, u64 a, u64 b) {
    asm("fma.rn.f32x2 %0, %1, %2, %0;" : "+l"(d) : "l"(a), "l"(b));
}
__device__ __forceinline__ float softplusf(float x) {
    return fmaxf(x, 0.0f) + log1pf(__expf(-fabsf(x)));
}
__device__ __forceinline__ uint32_t smem_u32(const void* p) {
    uint32_t a;
    asm("{ .reg .u64 t; cvta.to.shared.u64 t, %1; cvt.u32.u64 %0, t; }" : "=r"(a) : "l"(p));
    return a;
}
#define CP_ASYNC16(dst, src) \
    asm volatile("cp.async.cg.shared.global [%0], [%1], 16;" :: "r"(dst), "l"(src))
#define CP_COMMIT() asm volatile("cp.async.commit_group;" ::: "memory")
#define CP_WAIT0()  asm volatile("cp.async.wait_group 0;" ::: "memory")

// ---------------- tensor-core primitives (baseline ISA, sm_80+) ----------------
__device__ __forceinline__ void ldsm_x4(uint32_t addr, uint32_t r[4]) {
    asm volatile("ldmatrix.sync.aligned.m8n8.x4.shared.b16 {%0,%1,%2,%3}, [%4];"
                 : "=r"(r[0]), "=r"(r[1]), "=r"(r[2]), "=r"(r[3]) : "r"(addr));
}
__device__ __forceinline__ void mma16816(float d[4], const uint32_t a[4],
                                         uint32_t b0, uint32_t b1) {
    asm volatile("mma.sync.aligned.m16n8k16.row.col.f32.f16.f16.f32 "
                 "{%0,%1,%2,%3}, {%4,%5,%6,%7}, {%8,%9}, {%0,%1,%2,%3};"
                 : "+f"(d[0]), "+f"(d[1]), "+f"(d[2]), "+f"(d[3])
                 : "r"(a[0]), "r"(a[1]), "r"(a[2]), "r"(a[3]), "r"(b0), "r"(b1));
}
__device__ __forceinline__ uint32_t hpack(__half a, __half b) {
    uint32_t r;
    asm("mov.b32 %0, {%1, %2};" : "=r"(r) : "h"(__half_as_ushort(a)), "h"(__half_as_ushort(b)));
    return r;
}

// =====================================================================
// prep kernel: W3 [256 x 1568] -> per-lane hi B fragments per chunk
// =====================================================================
__global__ void prep_w3_kernel(const float* __restrict__ W3) {
    int id = blockIdx.x * blockDim.x + threadIdx.x;
    if (id >= NCH * 8 * 16 * 32) return;
    const int lane = id & 31;
    const int kk   = (id >> 5) & 15;
    const int nt   = (id >> 9) & 7;
    const int c    = id >> 12;
    const int g = lane >> 2, tg = lane & 3;
    const int n = nt * 8 + g;
    float w00 = 0.f, w01 = 0.f, w10 = 0.f, w11 = 0.f;
    if (n < 49) {
        const size_t pi = (size_t)c * 49 + n;
        const int k0 = kk * 16 + 2 * tg;
        w00 = W3[(size_t)(k0    ) * DOUT + pi];
        w01 = W3[(size_t)(k0 + 1) * DOUT + pi];
        w10 = W3[(size_t)(k0 + 8) * DOUT + pi];
        w11 = W3[(size_t)(k0 + 9) * DOUT + pi];
    }
    uint2 v;
    v.x = hpack(__float2half_rn(w00), __float2half_rn(w01));   // hi b0
    v.y = hpack(__float2half_rn(w10), __float2half_rn(w11));   // hi b1
    g_W3B[id] = v;
}

// =====================================================================
// main fused kernel
// =====================================================================
__global__ __launch_bounds__(THREADS, 1)
void rq_fused_kernel(const float* __restrict__ x1,
                     const float* __restrict__ x2,
                     const float* __restrict__ W1,
                     const float* __restrict__ b1,
                     const float* __restrict__ W2,
                     const float* __restrict__ b2,
                     const float* __restrict__ b3,
                     float* __restrict__ zout,
                     float* __restrict__ ldout)
{
    extern __shared__ char smem[];
    const uint32_t sbase = smem_u32(smem);
    float* x1s = (float*)(smem + SM_X1);
    float* h1T = (float*)(smem + SM_H1);
    float* prm = (float*)(smem + SM_PRM);
    float* b3s = (float*)(smem + SM_B3);

    const int t    = threadIdx.x;
    const int wid  = t >> 5;
    const int lane = t & 31;
    const int col  = t & 255;     // owned MLP column in phases 1-2 (warps 0-15)
    const int rh   = (t >> 8) & 1;
    const int row0 = blockIdx.x * MROWS;

    // b3 -> smem (region disjoint from phase scratch)
    for (int i = t; i < DOUT; i += THREADS) b3s[i] = b3[i];

    // ---------------- phases 1+2 (SIMT fp32x2, warps 0-15): 2 sub-blocks of 64 rows ----
    for (int sub = 0; sub < 2; sub++) {
        if (t < 512)
            for (int i = t; i < 64 * D1; i += 512)
                x1s[i] = x1[(size_t)(row0 + sub * 64) * D1 + i];
        __syncthreads();

        if (t < 512) {
            // phase 1: h1 = relu(x1 @ W1 + b1)
            float w1r[D1];
            #pragma unroll
            for (int k = 0; k < D1; k++) w1r[k] = W1[k * DFF + col];
            const float bb = b1[col];
            #pragma unroll
            for (int rr = 0; rr < 32; rr++) {
                const int r = rh * 32 + rr;
                float acc = bb;
                #pragma unroll
                for (int k = 0; k < D1; k++)
                    acc = fmaf(x1s[r * D1 + k], w1r[k], acc);
                h1T[col * HSTR + r] = fmaxf(acc, 0.0f);
            }
        }
        __syncthreads();

        if (t < 512) {
            // phase 2: h2 = relu(h1 @ W2 + b2) -> A_hi/A_lo f16 (XOR16-swizzled)
            u64 acc2[16];
            const float bb = b2[col];
            #pragma unroll
            for (int q = 0; q < 16; q++) acc2[q] = pack2(bb, bb);
            #pragma unroll 4
            for (int k = 0; k < DFF; k++) {
                const float w = __ldg(W2 + k * DFF + col);
                const u64 w2 = pack2(w, w);
                const ulonglong2* h4 = reinterpret_cast<const ulonglong2*>(
                    h1T + k * HSTR + rh * 32);
                #pragma unroll
                for (int q = 0; q < 8; q++) {
                    ulonglong2 a = h4[q];
                    fma2(acc2[2*q + 0], a.x, w2);
                    fma2(acc2[2*q + 1], a.y, w2);
                }
            }
            #pragma unroll
            for (int q = 0; q < 16; q++) {
                float lo, hi;
                unpack2(acc2[q], lo, hi);
                #pragma unroll
                for (int e = 0; e < 2; e++) {
                    const float v = fmaxf(e ? hi : lo, 0.0f);
                    const int r = sub * 64 + rh * 32 + 2 * q + e;
                    const __half vh = __float2half_rn(v);
                    const __half vl = __float2half_rn(v - __half2float(vh));
                    const uint32_t ao = (uint32_t)(r * 512 + col * 2) ^ ((uint32_t)(r & 7) << 4);
                    *(__half*)(smem + SM_A_HI + ao) = vh;
                    *(__half*)(smem + SM_A_LO + ao) = vl;
                }
            }
        }
        __syncthreads();
    }

    // preload B chunk 0 into buffer 0 via cp.async (32 KB = 2048 x 16B)
    {
        const uint4* src = (const uint4*)g_W3B;
        for (int i = t; i < B_TILE_U4; i += THREADS)
            CP_ASYNC16(sbase + SM_B0 + i * 16, (const void*)(src + i));
        CP_COMMIT(); CP_WAIT0();
    }
    __syncthreads();

    // =====================================================================
    // chunk pipeline (double-buffered B):
    //   warps 0-15 : issue cp.async B(c+1) -> buf[(c+1)&1], then MMA mainloop on buf[c&1]
    //   warps 16-19: spline for chunk c-1 (concurrent with MMA mainloop c)
    // =====================================================================
    float ldsum = 0.0f;

    const int mt = wid & 7;       // 16-row M-tile
    const int nh = wid >> 3;      // 32-col N-half
    const uint32_t arow  = (uint32_t)(mt * 16 + (lane & 15));
    const uint32_t abase = arow * 512 + ((lane >> 4) << 4);
    const uint32_t aswz  = (arow & 7) << 4;

    #pragma unroll 1
    for (int c = 0; c < NCH; c++) {
        float d[16];
        if (wid < 16) {
            // kick off B(c+1) prefetch into the other buffer (full 2048 uint4 tile)
            if (c + 1 < NCH) {
                const uint4* src = (const uint4*)g_W3B + (size_t)(c + 1) * B_TILE_U4;
                const uint32_t dst = sbase + (((c + 1) & 1) ? SM_B1 : SM_B0);
                #pragma unroll
                for (int q = 0; q < 4; q++) {
                    const int i = t + q * 512;   // 512 threads x 4 = 2048 uint4
                    CP_ASYNC16(dst + i * 16, (const void*)(src + i));
                }
            }
            CP_COMMIT();

            // ------------------ MMA mainloop on buf[c&1], double-buffered frags ------
            const uint2* Bsm = (const uint2*)(smem + ((c & 1) ? SM_B1 : SM_B0));
            #pragma unroll
            for (int i = 0; i < 16; i++) d[i] = 0.0f;

            uint32_t ah[2][4], al[2][4];
            uint2 bb[2][4];
            {   // preload kk = 0
                const uint32_t o = abase ^ aswz;
                ldsm_x4(sbase + SM_A_HI + o, ah[0]);
                ldsm_x4(sbase + SM_A_LO + o, al[0]);
                #pragma unroll
                for (int nt4 = 0; nt4 < 4; nt4++)
                    bb[0][nt4] = Bsm[((nh * 4 + nt4) * 16 + 0) * 32 + lane];
            }
            #pragma unroll
            for (int kk = 0; kk < 16; kk++) {
                const int cur = kk & 1, nxt = cur ^ 1;
                if (kk < 15) {
                    const uint32_t o = (abase + (kk + 1) * 32) ^ aswz;
                    ldsm_x4(sbase + SM_A_HI + o, ah[nxt]);
                    ldsm_x4(sbase + SM_A_LO + o, al[nxt]);
                    #pragma unroll
                    for (int nt4 = 0; nt4 < 4; nt4++)
                        bb[nxt][nt4] = Bsm[((nh * 4 + nt4) * 16 + (kk + 1)) * 32 + lane];
                }
                #pragma unroll
                for (int nt4 = 0; nt4 < 4; nt4++) {
                    mma16816(d + nt4 * 4, ah[cur], bb[cur][nt4].x, bb[cur][nt4].y); // hi*hi
                    mma16816(d + nt4 * 4, al[cur], bb[cur][nt4].x, bb[cur][nt4].y); // lo*hi
                }
            }
        } else if (c > 0) {
            // ------------------ spline warps: chunk c-1 ------------------
            const int rr   = t - 512;          // 0..127
            const int grow = row0 + rr;
            const int j    = c - 1;
            const float* pp = prm + rr * PRMSTR;

            const float x = __ldg(x2 + (size_t)grow * D2 + j);
            const bool inside = (x >= -TAILF) && (x <= TAILF);
            const float xc = fminf(fmaxf(x, -TAILF), TAILF);

            float mw = -1e30f, mh = -1e30f;
            #pragma unroll
            for (int i = 0; i < NBINS; i++) {
                mw = fmaxf(mw, pp[i]);
                mh = fmaxf(mh, pp[NBINS + i]);
            }
            float ew[NBINS], eh[NBINS];
            float sw = 0.0f, sh = 0.0f;
            #pragma unroll
            for (int i = 0; i < NBINS; i++) {
                ew[i] = __expf(pp[i] - mw);          sw += ew[i];
                eh[i] = __expf(pp[NBINS + i] - mh);  sh += eh[i];
            }
            const float cscale = 1.0f - NBINS * MINVF;
            const float rw = cscale / sw;
            const float rhh = cscale / sh;

            float S = 0.0f;
            float cw_lo = -TAILF, cw_lo_prev = -TAILF, cw_hi = TAILF;
            int idx = 0;
            bool failed = false;
            #pragma unroll
            for (int m = 1; m <= NBINS; m++) {
                S += MINVF + rw * ew[m - 1];
                const float cwm = fmaf(2.0f * TAILF, S, -TAILF);
                const float ref = (m == NBINS) ? (cwm + EPSF) : cwm;
                if (ref <= xc) { idx = m; cw_lo_prev = cw_lo; cw_lo = cwm; }
                else if (!failed) { failed = true; cw_hi = cwm; }
            }
            if (!failed) { idx = NBINS - 1; cw_hi = cw_lo; cw_lo = cw_lo_prev; }

            float Sh = 0.0f;
            float ch_lo = -TAILF, ch_hi = TAILF;
            #pragma unroll
            for (int m = 1; m <= NBINS; m++) {
                Sh += MINVF + rhh * eh[m - 1];
                const float chm = fmaf(2.0f * TAILF, Sh, -TAILF);
                if (m == idx)     ch_lo = chm;
                if (m == idx + 1) ch_hi = chm;
            }

            const float dd0 = MINVF + softplusf(pp[2 * NBINS + idx]);
            const float dd1 = MINVF + softplusf(pp[2 * NBINS + idx + 1]);

            const float xkd = cw_hi - cw_lo;
            const float ykd = ch_hi - ch_lo;
            const float sk  = ykd / xkd;
            const float xi  = (xc - cw_lo) / xkd;
            const float xi1m = xi * (1.0f - xi);
            const float alpha = ykd * (sk * xi * xi + dd0 * xi1m);
            const float beta  = sk + (dd1 + dd0 - 2.0f * sk) * xi1m;
            const float z     = ch_lo + alpha / beta;
            const float omxi  = 1.0f - xi;
            const float dnum  = sk * sk * (dd1 * xi * xi + 2.0f * sk * xi1m + dd0 * omxi * omxi);
            const float ld = __logf(dnum) - 2.0f * __logf(beta);

            zout[(size_t)grow * D2 + j] = inside ? z : x;
            ldsum += inside ? ld : 0.0f;
        }
        __syncthreads();   // mid-sync: spline(c-1) done -> prm free for epilogue

        if (wid < 16) {
            // ------------------ epilogue: D + b3 -> prm ------------------
            const int g = lane >> 2, tg = lane & 3;
            const int r0 = mt * 16 + g, r1 = r0 + 8;
            const float* b3c = b3s + c * 49;
            #pragma unroll
            for (int nt4 = 0; nt4 < 4; nt4++) {
                const int n0 = nh * 32 + nt4 * 8 + 2 * tg;
                if (n0 < 49) {
                    const float bv = b3c[n0];
                    prm[r0 * PRMSTR + n0] = d[nt4*4 + 0] + bv;
                    prm[r1 * PRMSTR + n0] = d[nt4*4 + 2] + bv;
                }
                if (n0 + 1 < 49) {
                    const float bv = b3c[n0 + 1];
                    prm[r0 * PRMSTR + n0 + 1] = d[nt4*4 + 1] + bv;
                    prm[r1 * PRMSTR + n0 + 1] = d[nt4*4 + 3] + bv;
                }
            }
            CP_WAIT0();    // B(c+1) landed (issued a full mainloop ago)
        }
        __syncthreads();   // end-sync: prm(c) visible, B(c+1) ready
    }

    // final spline: chunk NCH-1
    if (wid >= 16) {
        const int rr   = t - 512;
        const int grow = row0 + rr;
        const int j    = NCH - 1;
        const float* pp = prm + rr * PRMSTR;

        const float x = __ldg(x2 + (size_t)grow * D2 + j);
        const bool inside = (x >= -TAILF) && (x <= TAILF);
        const float xc = fminf(fmaxf(x, -TAILF), TAILF);

        float mw = -1e30f, mh = -1e30f;
        #pragma unroll
        for (int i = 0; i < NBINS; i++) {
            mw = fmaxf(mw, pp[i]);
            mh = fmaxf(mh, pp[NBINS + i]);
        }
        float ew[NBINS], eh[NBINS];
        float sw = 0.0f, sh = 0.0f;
        #pragma unroll
        for (int i = 0; i < NBINS; i++) {
            ew[i] = __expf(pp[i] - mw);          sw += ew[i];
            eh[i] = __expf(pp[NBINS + i] - mh);  sh += eh[i];
        }
        const float cscale = 1.0f - NBINS * MINVF;
        const float rw = cscale / sw;
        const float rhh = cscale / sh;

        float S = 0.0f;
        float cw_lo = -TAILF, cw_lo_prev = -TAILF, cw_hi = TAILF;
        int idx = 0;
        bool failed = false;
        #pragma unroll
        for (int m = 1; m <= NBINS; m++) {
            S += MINVF + rw * ew[m - 1];
            const float cwm = fmaf(2.0f * TAILF, S, -TAILF);
            const float ref = (m == NBINS) ? (cwm + EPSF) : cwm;
            if (ref <= xc) { idx = m; cw_lo_prev = cw_lo; cw_lo = cwm; }
            else if (!failed) { failed = true; cw_hi = cwm; }
        }
        if (!failed) { idx = NBINS - 1; cw_hi = cw_lo; cw_lo = cw_lo_prev; }

        float Sh = 0.0f;
        float ch_lo = -TAILF, ch_hi = TAILF;
        #pragma unroll
        for (int m = 1; m <= NBINS; m++) {
            Sh += MINVF + rhh * eh[m - 1];
            const float chm = fmaf(2.0f * TAILF, Sh, -TAILF);
            if (m == idx)     ch_lo = chm;
            if (m == idx + 1) ch_hi = chm;
        }

        const float dd0 = MINVF + softplusf(pp[2 * NBINS + idx]);
        const float dd1 = MINVF + softplusf(pp[2 * NBINS + idx + 1]);

        const float xkd = cw_hi - cw_lo;
        const float ykd = ch_hi - ch_lo;
        const float sk  = ykd / xkd;
        const float xi  = (xc - cw_lo) / xkd;
        const float xi1m = xi * (1.0f - xi);
        const float alpha = ykd * (sk * xi * xi + dd0 * xi1m);
        const float beta  = sk + (dd1 + dd0 - 2.0f * sk) * xi1m;
        const float z     = ch_lo + alpha / beta;
        const float omxi  = 1.0f - xi;
        const float dnum  = sk * sk * (dd1 * xi * xi + 2.0f * sk * xi1m + dd0 * omxi * omxi);
        const float ld = __logf(dnum) - 2.0f * __logf(beta);

        zout[(size_t)grow * D2 + j] = inside ? z : x;
        ldsum += inside ? ld : 0.0f;

        ldout[grow] = ldsum;
    }
}

extern "C" void kernel_launch(void* const* d_in, const int* in_sizes, int n_in,
                              void* d_out, int out_size)
{
    const float* x1 = (const float*)d_in[0];
    const float* x2 = (const float*)d_in[1];
    const float* W1 = (const float*)d_in[2];
    const float* b1 = (const float*)d_in[3];
    const float* W2 = (const float*)d_in[4];
    const float* b2 = (const float*)d_in[5];
    const float* W3 = (const float*)d_in[6];
    const float* b3 = (const float*)d_in[7];

    float* out = (float*)d_out;
    const int B = in_sizes[0] / D1;         // 65536
    float* zout  = out;
    float* ldout = out + (size_t)B * D2;

    prep_w3_kernel<<<(NCH * 8 * 16 * 32 + 255) / 256, 256>>>(W3);

    cudaFuncSetAttribute(rq_fused_kernel,
                         cudaFuncAttributeMaxDynamicSharedMemorySize, SMEM_TOTAL);
    rq_fused_kernel<<<B / MROWS, THREADS, SMEM_TOTAL>>>(
        x1, x2, W1, b1, W2, b2, b3, zout, ldout);
}

// round 10
// speedup vs baseline: 1.4338x; 1.1028x over previous
#include <cuda_runtime.h>
#include <cuda_fp16.h>
#include <math.h>
#include <stdint.h>

// ---------------- problem constants ----------------
#define THREADS   320
#define MROWS     64          // batch rows per CTA (2 CTAs/SM)
#define D1        32
#define DFF       256
#define D2        32
#define NBINS     16
#define DOUT      1568        // 49*32
#define NCH       32          // one chunk per output j
#define NTILES    7           // n8 tiles per chunk (49 -> 56 padded)
#define HSTR      36          // h1T padded stride (floats)
#define PRMSTR    51          // prm stride (floats), odd -> conflict-free spline reads
#define TAILF     3.0f
#define MINVF     0.001f
#define EPSF      1e-6f

// ---------------- smem byte offsets (total 107264 per CTA) ----------------
#define SM_A_HI   0                         // 64x256 f16, 512B/row, XOR16 swizzle (32768 B)
#define SM_A_LO   32768                     // 32768 B
#define SM_B      65536                     // B tile 7*16*32 uint2 = 28672 B
#define SM_PRM    94208                     // 64x51 f32 = 13056 B  (ends 107264)
// phase-only overlays (B+prm region unused during phases):
#define SM_H1     65536                     // 256x36 f32 = 36864 B (ends 102400)
#define SM_X1     102400                    // 32x32 f32 = 4096 B   (ends 106496)
#define SMEM_TOTAL 107264

#define B_TILE_U2 (NTILES * 16 * 32)        // 3584 uint2 per chunk
#define B_TILE_U4 (B_TILE_U2 / 2)           // 1792 uint4

typedef unsigned long long u64;

// prepped W3 hi-fragments: [c][nt][kk][lane] -> uint2{hi_b0, hi_b1}
__device__ __align__(16) uint2 g_W3B[NCH * NTILES * 16 * 32];   // 917504 B

// ---------------- helpers ----------------
__device__ __forceinline__ u64 pack2(float lo, float hi) {
    u64 r; asm("mov.b64 %0, {%1, %2};" : "=l"(r) : "f"(lo), "f"(hi)); return r;
}
__device__ __forceinline__ void unpack2(u64 v, float& lo, float& hi) {
    asm("mov.b64 {%0, %1}, %2;" : "=f"(lo), "=f"(hi) : "l"(v));
}
__device__ __forceinline__ void fma2(u64& d, u64 a, u64 b) {
    asm("fma.rn.f32x2 %0, %1, %2, %0;" : "+l"(d) : "l"(a), "l"(b));
}
__device__ __forceinline__ float softplusf(float x) {
    return fmaxf(x, 0.0f) + log1pf(__expf(-fabsf(x)));
}
__device__ __forceinline__ uint32_t smem_u32(const void* p) {
    uint32_t a;
    asm("{ .reg .u64 t; cvta.to.shared.u64 t, %1; cvt.u32.u64 %0, t; }" : "=r"(a) : "l"(p));
    return a;
}
#define CP_ASYNC16(dst, src) \
    asm volatile("cp.async.cg.shared.global [%0], [%1], 16;" :: "r"(dst), "l"(src))
#define CP_COMMIT() asm volatile("cp.async.commit_group;" ::: "memory")
#define CP_WAIT0()  asm volatile("cp.async.wait_group 0;" ::: "memory")

// ---------------- tensor-core primitives (baseline ISA, sm_80+) ----------------
__device__ __forceinline__ void ldsm_x4(uint32_t addr, uint32_t r[4]) {
    asm volatile("ldmatrix.sync.aligned.m8n8.x4.shared.b16 {%0,%1,%2,%3}, [%4];"
                 : "=r"(r[0]), "=r"(r[1]), "=r"(r[2]), "=r"(r[3]) : "r"(addr));
}
__device__ __forceinline__ void mma16816(float d[4], const uint32_t a[4],
                                         uint32_t b0, uint32_t b1) {
    asm volatile("mma.sync.aligned.m16n8k16.row.col.f32.f16.f16.f32 "
                 "{%0,%1,%2,%3}, {%4,%5,%6,%7}, {%8,%9}, {%0,%1,%2,%3};"
                 : "+f"(d[0]), "+f"(d[1]), "+f"(d[2]), "+f"(d[3])
                 : "r"(a[0]), "r"(a[1]), "r"(a[2]), "r"(a[3]), "r"(b0), "r"(b1));
}
__device__ __forceinline__ uint32_t hpack(__half a, __half b) {
    uint32_t r;
    asm("mov.b32 %0, {%1, %2};" : "=r"(r) : "h"(__half_as_ushort(a)), "h"(__half_as_ushort(b)));
    return r;
}

// =====================================================================
// prep kernel: W3 [256 x 1568] -> per-lane hi B fragments, 7 tiles/chunk
// =====================================================================
__global__ void prep_w3_kernel(const float* __restrict__ W3) {
    int id = blockIdx.x * blockDim.x + threadIdx.x;
    if (id >= NCH * NTILES * 16 * 32) return;
    const int lane = id & 31;
    const int kk   = (id >> 5) & 15;
    const int rest = id >> 9;
    const int nt   = rest % NTILES;
    const int c    = rest / NTILES;
    const int g = lane >> 2, tg = lane & 3;
    const int n = nt * 8 + g;                 // 0..55
    float w00 = 0.f, w01 = 0.f, w10 = 0.f, w11 = 0.f;
    if (n < 49) {
        const size_t pi = (size_t)c * 49 + n;
        const int k0 = kk * 16 + 2 * tg;
        w00 = W3[(size_t)(k0    ) * DOUT + pi];
        w01 = W3[(size_t)(k0 + 1) * DOUT + pi];
        w10 = W3[(size_t)(k0 + 8) * DOUT + pi];
        w11 = W3[(size_t)(k0 + 9) * DOUT + pi];
    }
    uint2 v;
    v.x = hpack(__float2half_rn(w00), __float2half_rn(w01));
    v.y = hpack(__float2half_rn(w10), __float2half_rn(w11));
    g_W3B[((c * NTILES + nt) * 16 + kk) * 32 + lane] = v;
}

// =====================================================================
// main fused kernel: 2 CTAs per SM
// =====================================================================
__global__ __launch_bounds__(THREADS, 2)
void rq_fused_kernel(const float* __restrict__ x1,
                     const float* __restrict__ x2,
                     const float* __restrict__ W1,
                     const float* __restrict__ b1,
                     const float* __restrict__ W2,
                     const float* __restrict__ b2,
                     const float* __restrict__ b3,
                     float* __restrict__ zout,
                     float* __restrict__ ldout)
{
    extern __shared__ char smem[];
    const uint32_t sbase = smem_u32(smem);
    float* x1s = (float*)(smem + SM_X1);
    float* h1T = (float*)(smem + SM_H1);
    float* prm = (float*)(smem + SM_PRM);
    const uint2* Bsm = (const uint2*)(smem + SM_B);

    const int t    = threadIdx.x;
    const int wid  = t >> 5;
    const int lane = t & 31;
    const int row0 = blockIdx.x * MROWS;

    // ---------------- phases 1+2 (SIMT fp32x2, threads 0-255): 2 sub-blocks of 32 rows
    for (int sub = 0; sub < 2; sub++) {
        if (t < 256)
            for (int i = t; i < 32 * D1; i += 256)
                x1s[i] = x1[(size_t)(row0 + sub * 32) * D1 + i];
        __syncthreads();

        if (t < 256) {
            const int col = t;
            // phase 1: h1 = relu(x1 @ W1 + b1), 32 rows
            float w1r[D1];
            #pragma unroll
            for (int k = 0; k < D1; k++) w1r[k] = W1[k * DFF + col];
            const float bb = b1[col];
            #pragma unroll
            for (int rr = 0; rr < 32; rr++) {
                float acc = bb;
                #pragma unroll
                for (int k = 0; k < D1; k++)
                    acc = fmaf(x1s[rr * D1 + k], w1r[k], acc);
                h1T[col * HSTR + rr] = fmaxf(acc, 0.0f);
            }
        }
        __syncthreads();

        if (t < 256) {
            const int col = t;
            // phase 2: h2 = relu(h1 @ W2 + b2) -> A_hi/A_lo f16 (XOR16-swizzled)
            u64 acc2[16];
            const float bb = b2[col];
            #pragma unroll
            for (int q = 0; q < 16; q++) acc2[q] = pack2(bb, bb);
            #pragma unroll 4
            for (int k = 0; k < DFF; k++) {
                const float w = __ldg(W2 + k * DFF + col);
                const u64 w2 = pack2(w, w);
                const ulonglong2* h4 = reinterpret_cast<const ulonglong2*>(h1T + k * HSTR);
                #pragma unroll
                for (int q = 0; q < 8; q++) {
                    ulonglong2 a = h4[q];
                    fma2(acc2[2*q + 0], a.x, w2);
                    fma2(acc2[2*q + 1], a.y, w2);
                }
            }
            #pragma unroll
            for (int q = 0; q < 16; q++) {
                float lo, hi;
                unpack2(acc2[q], lo, hi);
                #pragma unroll
                for (int e = 0; e < 2; e++) {
                    const float v = fmaxf(e ? hi : lo, 0.0f);
                    const int r = sub * 32 + 2 * q + e;
                    const __half vh = __float2half_rn(v);
                    const __half vl = __float2half_rn(v - __half2float(vh));
                    const uint32_t ao = (uint32_t)(r * 512 + col * 2) ^ ((uint32_t)(r & 7) << 4);
                    *(__half*)(smem + SM_A_HI + ao) = vh;
                    *(__half*)(smem + SM_A_LO + ao) = vl;
                }
            }
        }
        __syncthreads();
    }

    // preload B chunk 0 (28672 B = 1792 uint4)
    {
        const uint4* src = (const uint4*)g_W3B;
        for (int i = t; i < B_TILE_U4; i += THREADS)
            CP_ASYNC16(sbase + SM_B + i * 16, (const void*)(src + i));
        CP_COMMIT(); CP_WAIT0();
    }
    __syncthreads();

    // =====================================================================
    // chunk pipeline (single B buffer, refilled between syncs):
    //   warps 0-7 : MMA (M=16 rows x N=32/24 cols); mainloop(c) || spline(c-1)
    //   warps 8-9 : spline for chunk c-1
    // =====================================================================
    float ldsum = 0.0f;

    const int mt = wid & 3;        // 16-row M-tile (0-3)
    const int nh = wid >> 2;       // 0: tiles 0-3, 1: tiles 4-6
    const int tbase = nh * 4;
    const uint32_t arow  = (uint32_t)(mt * 16 + (lane & 15));
    const uint32_t abase = arow * 512 + ((lane >> 4) << 4);
    const uint32_t aswz  = (arow & 7) << 4;

    #pragma unroll 1
    for (int c = 0; c < NCH; c++) {
        float d[16];
        if (wid < 8) {
            // ------------------ MMA mainloop, double-buffered frags ------------------
            #pragma unroll
            for (int i = 0; i < 16; i++) d[i] = 0.0f;

            uint32_t ah[2][4], al[2][4];
            uint2 bb[2][4];
            {   // preload kk = 0
                const uint32_t o = abase ^ aswz;
                ldsm_x4(sbase + SM_A_HI + o, ah[0]);
                ldsm_x4(sbase + SM_A_LO + o, al[0]);
                #pragma unroll
                for (int nt4 = 0; nt4 < 4; nt4++)
                    if (tbase + nt4 < NTILES)
                        bb[0][nt4] = Bsm[((tbase + nt4) * 16 + 0) * 32 + lane];
            }
            #pragma unroll
            for (int kk = 0; kk < 16; kk++) {
                const int cur = kk & 1, nxt = cur ^ 1;
                if (kk < 15) {
                    const uint32_t o = (abase + (kk + 1) * 32) ^ aswz;
                    ldsm_x4(sbase + SM_A_HI + o, ah[nxt]);
                    ldsm_x4(sbase + SM_A_LO + o, al[nxt]);
                    #pragma unroll
                    for (int nt4 = 0; nt4 < 4; nt4++)
                        if (tbase + nt4 < NTILES)
                            bb[nxt][nt4] = Bsm[((tbase + nt4) * 16 + (kk + 1)) * 32 + lane];
                }
                #pragma unroll
                for (int nt4 = 0; nt4 < 4; nt4++)
                    if (tbase + nt4 < NTILES) {
                        mma16816(d + nt4 * 4, ah[cur], bb[cur][nt4].x, bb[cur][nt4].y); // hi*hi
                        mma16816(d + nt4 * 4, al[cur], bb[cur][nt4].x, bb[cur][nt4].y); // lo*hi
                    }
            }
        } else if (c > 0) {
            // ------------------ spline warps: chunk c-1, row rr = t-256 --------------
            const int rr   = t - 256;          // 0..63
            const int grow = row0 + rr;
            const int j    = c - 1;
            const float* pp = prm + rr * PRMSTR;

            const float x = __ldg(x2 + (size_t)grow * D2 + j);
            const bool inside = (x >= -TAILF) && (x <= TAILF);
            const float xc = fminf(fmaxf(x, -TAILF), TAILF);

            float mw = -1e30f, mh = -1e30f;
            #pragma unroll
            for (int i = 0; i < NBINS; i++) {
                mw = fmaxf(mw, pp[i]);
                mh = fmaxf(mh, pp[NBINS + i]);
            }
            float ew[NBINS], eh[NBINS];
            float sw = 0.0f, sh = 0.0f;
            #pragma unroll
            for (int i = 0; i < NBINS; i++) {
                ew[i] = __expf(pp[i] - mw);          sw += ew[i];
                eh[i] = __expf(pp[NBINS + i] - mh);  sh += eh[i];
            }
            const float cscale = 1.0f - NBINS * MINVF;
            const float rw = cscale / sw;
            const float rhh = cscale / sh;

            float S = 0.0f;
            float cw_lo = -TAILF, cw_lo_prev = -TAILF, cw_hi = TAILF;
            int idx = 0;
            bool failed = false;
            #pragma unroll
            for (int m = 1; m <= NBINS; m++) {
                S += MINVF + rw * ew[m - 1];
                const float cwm = fmaf(2.0f * TAILF, S, -TAILF);
                const float ref = (m == NBINS) ? (cwm + EPSF) : cwm;
                if (ref <= xc) { idx = m; cw_lo_prev = cw_lo; cw_lo = cwm; }
                else if (!failed) { failed = true; cw_hi = cwm; }
            }
            if (!failed) { idx = NBINS - 1; cw_hi = cw_lo; cw_lo = cw_lo_prev; }

            float Sh = 0.0f;
            float ch_lo = -TAILF, ch_hi = TAILF;
            #pragma unroll
            for (int m = 1; m <= NBINS; m++) {
                Sh += MINVF + rhh * eh[m - 1];
                const float chm = fmaf(2.0f * TAILF, Sh, -TAILF);
                if (m == idx)     ch_lo = chm;
                if (m == idx + 1) ch_hi = chm;
            }

            const float dd0 = MINVF + softplusf(pp[2 * NBINS + idx]);
            const float dd1 = MINVF + softplusf(pp[2 * NBINS + idx + 1]);

            const float xkd = cw_hi - cw_lo;
            const float ykd = ch_hi - ch_lo;
            const float sk  = ykd / xkd;
            const float xi  = (xc - cw_lo) / xkd;
            const float xi1m = xi * (1.0f - xi);
            const float alpha = ykd * (sk * xi * xi + dd0 * xi1m);
            const float beta  = sk + (dd1 + dd0 - 2.0f * sk) * xi1m;
            const float z     = ch_lo + alpha / beta;
            const float omxi  = 1.0f - xi;
            const float dnum  = sk * sk * (dd1 * xi * xi + 2.0f * sk * xi1m + dd0 * omxi * omxi);
            const float ld = __logf(dnum) - 2.0f * __logf(beta);

            zout[(size_t)grow * D2 + j] = inside ? z : x;
            ldsum += inside ? ld : 0.0f;
        }
        __syncthreads();   // B(c) reads done; spline(c-1) done -> prm free

        if (wid < 8) {
            // refill B with chunk c+1 (single buffer, safe: no reader until next sync)
            if (c + 1 < NCH) {
                const uint4* src = (const uint4*)g_W3B + (size_t)(c + 1) * B_TILE_U4;
                #pragma unroll
                for (int q = 0; q < 7; q++) {
                    const int i = t + q * 256;   // 256 threads x 7 = 1792
                    CP_ASYNC16(sbase + SM_B + i * 16, (const void*)(src + i));
                }
            }
            CP_COMMIT();

            // ------------------ epilogue: D + b3 -> prm ------------------
            const int g = lane >> 2, tg = lane & 3;
            const int r0 = mt * 16 + g, r1 = r0 + 8;
            const float* b3c = b3 + c * 49;
            #pragma unroll
            for (int nt4 = 0; nt4 < 4; nt4++) {
                if (tbase + nt4 >= NTILES) continue;
                const int n0 = (tbase + nt4) * 8 + 2 * tg;
                if (n0 < 49) {
                    const float bv = __ldg(b3c + n0);
                    prm[r0 * PRMSTR + n0] = d[nt4*4 + 0] + bv;
                    prm[r1 * PRMSTR + n0] = d[nt4*4 + 2] + bv;
                }
                if (n0 + 1 < 49) {
                    const float bv = __ldg(b3c + n0 + 1);
                    prm[r0 * PRMSTR + n0 + 1] = d[nt4*4 + 1] + bv;
                    prm[r1 * PRMSTR + n0 + 1] = d[nt4*4 + 3] + bv;
                }
            }
            CP_WAIT0();    // B(c+1) landed (issued before epilogue)
        }
        __syncthreads();   // prm(c) visible, B(c+1) ready
    }

    // final spline: chunk NCH-1
    if (wid >= 8) {
        const int rr   = t - 256;
        const int grow = row0 + rr;
        const int j    = NCH - 1;
        const float* pp = prm + rr * PRMSTR;

        const float x = __ldg(x2 + (size_t)grow * D2 + j);
        const bool inside = (x >= -TAILF) && (x <= TAILF);
        const float xc = fminf(fmaxf(x, -TAILF), TAILF);

        float mw = -1e30f, mh = -1e30f;
        #pragma unroll
        for (int i = 0; i < NBINS; i++) {
            mw = fmaxf(mw, pp[i]);
            mh = fmaxf(mh, pp[NBINS + i]);
        }
        float ew[NBINS], eh[NBINS];
        float sw = 0.0f, sh = 0.0f;
        #pragma unroll
        for (int i = 0; i < NBINS; i++) {
            ew[i] = __expf(pp[i] - mw);          sw += ew[i];
            eh[i] = __expf(pp[NBINS + i] - mh);  sh += eh[i];
        }
        const float cscale = 1.0f - NBINS * MINVF;
        const float rw = cscale / sw;
        const float rhh = cscale / sh;

        float S = 0.0f;
        float cw_lo = -TAILF, cw_lo_prev = -TAILF, cw_hi = TAILF;
        int idx = 0;
        bool failed = false;
        #pragma unroll
        for (int m = 1; m <= NBINS; m++) {
            S += MINVF + rw * ew[m - 1];
            const float cwm = fmaf(2.0f * TAILF, S, -TAILF);
            const float ref = (m == NBINS) ? (cwm + EPSF) : cwm;
            if (ref <= xc) { idx = m; cw_lo_prev = cw_lo; cw_lo = cwm; }
            else if (!failed) { failed = true; cw_hi = cwm; }
        }
        if (!failed) { idx = NBINS - 1; cw_hi = cw_lo; cw_lo = cw_lo_prev; }

        float Sh = 0.0f;
        float ch_lo = -TAILF, ch_hi = TAILF;
        #pragma unroll
        for (int m = 1; m <= NBINS; m++) {
            Sh += MINVF + rhh * eh[m - 1];
            const float chm = fmaf(2.0f * TAILF, Sh, -TAILF);
            if (m == idx)     ch_lo = chm;
            if (m == idx + 1) ch_hi = chm;
        }

        const float dd0 = MINVF + softplusf(pp[2 * NBINS + idx]);
        const float dd1 = MINVF + softplusf(pp[2 * NBINS + idx + 1]);

        const float xkd = cw_hi - cw_lo;
        const float ykd = ch_hi - ch_lo;
        const float sk  = ykd / xkd;
        const float xi  = (xc - cw_lo) / xkd;
        const float xi1m = xi * (1.0f - xi);
        const float alpha = ykd * (sk * xi * xi + dd0 * xi1m);
        const float beta  = sk + (dd1 + dd0 - 2.0f * sk) * xi1m;
        const float z     = ch_lo + alpha / beta;
        const float omxi  = 1.0f - xi;
        const float dnum  = sk * sk * (dd1 * xi * xi + 2.0f * sk * xi1m + dd0 * omxi * omxi);
        const float ld = __logf(dnum) - 2.0f * __logf(beta);

        zout[(size_t)grow * D2 + j] = inside ? z : x;
        ldsum += inside ? ld : 0.0f;

        ldout[grow] = ldsum;
    }
}

extern "C" void kernel_launch(void* const* d_in, const int* in_sizes, int n_in,
                              void* d_out, int out_size)
{
    const float* x1 = (const float*)d_in[0];
    const float* x2 = (const float*)d_in[1];
    const float* W1 = (const float*)d_in[2];
    const float* b1 = (const float*)d_in[3];
    const float* W2 = (const float*)d_in[4];
    const float* b2 = (const float*)d_in[5];
    const float* W3 = (const float*)d_in[6];
    const float* b3 = (const float*)d_in[7];

    float* out = (float*)d_out;
    const int B = in_sizes[0] / D1;         // 65536
    float* zout  = out;
    float* ldout = out + (size_t)B * D2;

    prep_w3_kernel<<<(NCH * NTILES * 16 * 32 + 255) / 256, 256>>>(W3);

    cudaFuncSetAttribute(rq_fused_kernel,
                         cudaFuncAttributeMaxDynamicSharedMemorySize, SMEM_TOTAL);
    rq_fused_kernel<<<B / MROWS, THREADS, SMEM_TOTAL>>>(
        x1, x2, W1, b1, W2, b2, b3, zout, ldout);
}